// round 4
// baseline (speedup 1.0000x reference)
#include <cuda_runtime.h>

// ---------------- problem constants ----------------
#define B_   16
#define N_   10000
#define C_   256
#define H_   4
#define KD_  16
#define E_   320000
#define F_   1024          // B*H*KD per-node feature width
#define M_   (B_*N_)       // 160000 rows

// ---------------- device scratch (allocation-free rule: __device__ globals) ----
__device__ float g_q   [(size_t)M_*64];    // [r=b*N+n][h*16+kd]
__device__ float g_v   [(size_t)M_*256];   // [r][c]
__device__ float g_ping[(size_t)N_*F_];    // it buffers [n][b*64+h*16+kd]
__device__ float g_pong[(size_t)N_*F_];
__device__ float g_acc [(size_t)N_*F_];    // accumulated k
__device__ int   g_rowptr[N_+1];
__device__ int   g_fill  [N_];
__device__ int   g_cols  [E_];
__device__ float g_vals  [E_];

// ---------------- CSR build ----------------
__global__ void k_zero_counts() {
    int i = blockIdx.x*blockDim.x + threadIdx.x;
    if (i < N_) g_fill[i] = 0;
}

__global__ void k_hist(const int* __restrict__ rows) {
    int e = blockIdx.x*blockDim.x + threadIdx.x;
    if (e < E_) atomicAdd(&g_fill[rows[e]], 1);
}

// single-block exclusive scan over N_=10000 counts (10 chunks of 1024)
__global__ void k_scan() {
    __shared__ int sm[1024];
    int carry = 0;
    int tid = threadIdx.x;
    for (int base = 0; base < N_; base += 1024) {
        int idx = base + tid;
        int v = (idx < N_) ? g_fill[idx] : 0;
        sm[tid] = v;
        __syncthreads();
        for (int off = 1; off < 1024; off <<= 1) {
            int t = (tid >= off) ? sm[tid-off] : 0;
            __syncthreads();
            sm[tid] += t;
            __syncthreads();
        }
        int incl = sm[tid];
        if (idx < N_) {
            int ex = carry + incl - v;
            g_rowptr[idx] = ex;
            g_fill[idx]   = ex;   // reuse as scatter cursor
        }
        carry += sm[1023];
        __syncthreads();
    }
    if (tid == 0) g_rowptr[N_] = carry;
}

__global__ void k_scatter(const int* __restrict__ rows, const int* __restrict__ cols,
                          const float* __restrict__ vals) {
    int e = blockIdx.x*blockDim.x + threadIdx.x;
    if (e < E_) {
        int r = rows[e];
        int pos = atomicAdd(&g_fill[r], 1);
        g_cols[pos] = cols[e];
        g_vals[pos] = vals[e];
    }
}

// ---------------- fused GEMM: k/q (elu+1) + v ----------------
// grid.y = 0 : cols 0..63 = k (-> g_ping & g_acc), 64..127 = q
// grid.y = 1,2 : v cols (ct-1)*128 .. +128
__global__ __launch_bounds__(256) void k_gemm(const float* __restrict__ x,
                                              const float* __restrict__ Wk,
                                              const float* __restrict__ Wq,
                                              const float* __restrict__ Wv) {
    __shared__ float As[16][132];   // [k][m], padded
    __shared__ float Bs[16][128];   // [k][c]
    const int tid = threadIdx.x;
    const int m0  = blockIdx.x * 128;
    const int ct  = blockIdx.y;
    const int tx  = tid & 15;       // 8 cols each
    const int ty  = tid >> 4;       // 8 rows each

    float acc[8][8];
    #pragma unroll
    for (int i = 0; i < 8; i++)
        #pragma unroll
        for (int j = 0; j < 8; j++) acc[i][j] = 0.f;

    for (int k0 = 0; k0 < 256; k0 += 16) {
        // A tile: 128 rows x 16 k (transposed into smem)
        #pragma unroll
        for (int i = 0; i < 2; i++) {
            int idx = tid + 256*i;          // 512 float4 total
            int r = idx >> 2, q = idx & 3;
            float4 a4 = *(const float4*)(x + (size_t)(m0 + r)*256 + k0 + q*4);
            As[q*4+0][r] = a4.x; As[q*4+1][r] = a4.y;
            As[q*4+2][r] = a4.z; As[q*4+3][r] = a4.w;
        }
        // B tile: 16 k x 128 cols
        #pragma unroll
        for (int i = 0; i < 2; i++) {
            int idx = tid + 256*i;
            int kk = idx >> 5, q = idx & 31;
            int c = q * 4;
            float4 b4;
            if (ct == 0) {
                if (c < 64) b4 = *(const float4*)(Wk + (k0+kk)*64 + c);
                else        b4 = *(const float4*)(Wq + (k0+kk)*64 + (c-64));
            } else {
                b4 = *(const float4*)(Wv + (k0+kk)*256 + (ct-1)*128 + c);
            }
            *(float4*)&Bs[kk][c] = b4;
        }
        __syncthreads();
        #pragma unroll
        for (int kk = 0; kk < 16; kk++) {
            float a[8], b[8];
            *(float4*)&a[0] = *(const float4*)&As[kk][ty*8];
            *(float4*)&a[4] = *(const float4*)&As[kk][ty*8+4];
            *(float4*)&b[0] = *(const float4*)&Bs[kk][tx*8];
            *(float4*)&b[4] = *(const float4*)&Bs[kk][tx*8+4];
            #pragma unroll
            for (int i = 0; i < 8; i++)
                #pragma unroll
                for (int j = 0; j < 8; j++)
                    acc[i][j] = fmaf(a[i], b[j], acc[i][j]);
        }
        __syncthreads();
    }

    if (ct == 0) {
        #pragma unroll
        for (int i = 0; i < 8; i++) {
            int m = m0 + ty*8 + i;
            int bb = m / N_, nn = m % N_;
            #pragma unroll
            for (int j = 0; j < 8; j++) {
                int c = tx*8 + j;
                float val = acc[i][j];
                val = (val > 0.f) ? (val + 1.f) : __expf(val);   // elu(x)+1
                if (c < 64) {
                    int o = nn*F_ + bb*64 + c;
                    g_ping[o] = val;
                    g_acc[o]  = val;
                } else {
                    g_q[(size_t)m*64 + (c - 64)] = val;
                }
            }
        }
    } else {
        int cb = (ct - 1) * 128;
        #pragma unroll
        for (int i = 0; i < 8; i++) {
            int m = m0 + ty*8 + i;
            #pragma unroll
            for (int j = 0; j < 8; j++)
                g_v[(size_t)m*256 + cb + tx*8 + j] = acc[i][j];
        }
    }
}

// ---------------- sparse propagation: one block per row, register accumulators ----
__device__ __forceinline__ float4 f4fma(float s, float4 x, float4 a) {
    a.x = fmaf(s, x.x, a.x); a.y = fmaf(s, x.y, a.y);
    a.z = fmaf(s, x.z, a.z); a.w = fmaf(s, x.w, a.w);
    return a;
}

__global__ __launch_bounds__(128) void k_spmm(int srcsel, int store) {
    const float4* __restrict__ S = (const float4*)(srcsel ? g_pong : g_ping);
    float4* __restrict__ D       = (float4*)(srcsel ? g_ping : g_pong);
    const int r = blockIdx.x;
    const int t = threadIdx.x;                   // 128 threads x (2 float4) = 1024 floats
    const int e0 = g_rowptr[r], e1 = g_rowptr[r+1];

    float4 s0 = make_float4(0.f,0.f,0.f,0.f);
    float4 s1 = make_float4(0.f,0.f,0.f,0.f);

    #pragma unroll 4
    for (int e = e0; e < e1; e++) {
        int   c = __ldg(&g_cols[e]);
        float v = __ldg(&g_vals[e]);
        const float4* p = S + (size_t)c * 256;
        s0 = f4fma(v, __ldg(&p[t]),       s0);
        s1 = f4fma(v, __ldg(&p[128 + t]), s1);
    }

    // decay factored out: feature j = t*4 (and 512+t*4): head = (t%16)/4, same for all 4+4
    const int   h   = (t & 15) >> 2;
    const float dec = 0.1f + (float)h * (0.4f/3.0f);
    s0.x *= dec; s0.y *= dec; s0.z *= dec; s0.w *= dec;
    s1.x *= dec; s1.y *= dec; s1.z *= dec; s1.w *= dec;

    float4* A = (float4*)g_acc + (size_t)r * 256;
    float4 a0 = A[t];       a0.x += s0.x; a0.y += s0.y; a0.z += s0.z; a0.w += s0.w; A[t] = a0;
    float4 a1 = A[128 + t]; a1.x += s1.x; a1.y += s1.y; a1.z += s1.z; a1.w += s1.w; A[128 + t] = a1;

    if (store) {
        D[(size_t)r*256 + t]       = s0;
        D[(size_t)r*256 + 128 + t] = s1;
    }
}

// ---------------- fused epilogue: w = mean(k*q), scale v, LayerNorm, shuffled write ----
__global__ __launch_bounds__(128) void k_final(const float* __restrict__ gamma,
                                               const float* __restrict__ beta,
                                               float* __restrict__ out) {
    const int r  = blockIdx.x;        // r = b*N + n
    const int bb = r / N_, nn = r % N_;
    const int w  = threadIdx.x >> 5;  // head
    const int l  = threadIdx.x & 31;

    float p = 0.f;
    if (l < 16)
        p = g_acc[nn*F_ + bb*64 + w*16 + l] * g_q[(size_t)r*64 + w*16 + l];
    #pragma unroll
    for (int off = 16; off; off >>= 1) p += __shfl_xor_sync(0xffffffffu, p, off);
    const float wv = p * (1.0f/16.0f);

    const float* vp = g_v + (size_t)r*256 + w*64;
    float v0 = vp[l]      * wv;
    float v1 = vp[32 + l] * wv;

    float s  = v0 + v1;
    float s2 = fmaf(v0, v0, v1*v1);
    #pragma unroll
    for (int off = 16; off; off >>= 1) {
        s  += __shfl_xor_sync(0xffffffffu, s,  off);
        s2 += __shfl_xor_sync(0xffffffffu, s2, off);
    }
    const float mu  = s  * (1.0f/64.0f);
    const float var = s2 * (1.0f/64.0f) - mu*mu;
    const float inv = rsqrtf(var + 1e-5f);

    // out row shuffle from reshape(N,B,OUT).swapaxes(0,1)
    float* op = out + (size_t)((r % B_)*N_ + r / B_) * 256 + w*64;
    op[l]      = (v0 - mu)*inv*gamma[l]      + beta[l];
    op[32 + l] = (v1 - mu)*inv*gamma[32 + l] + beta[32 + l];
}

// ---------------- launch ----------------
extern "C" void kernel_launch(void* const* d_in, const int* in_sizes, int n_in,
                              void* d_out, int out_size) {
    const float* x     = (const float*)d_in[0];
    const float* evals = (const float*)d_in[1];
    const float* Wk    = (const float*)d_in[2];
    const float* Wq    = (const float*)d_in[3];
    const float* Wv    = (const float*)d_in[4];
    const float* gamma = (const float*)d_in[5];
    const float* beta  = (const float*)d_in[6];
    const int*   erows = (const int*)d_in[7];
    const int*   ecols = (const int*)d_in[8];
    float* out = (float*)d_out;

    // CSR build (re-done each replay; cheap)
    k_zero_counts<<<(N_ + 255)/256, 256>>>();
    k_hist<<<(E_ + 255)/256, 256>>>(erows);
    k_scan<<<1, 1024>>>();
    k_scatter<<<(E_ + 255)/256, 256>>>(erows, ecols, evals);

    // k/q/v GEMM with elu+1 epilogue; writes g_ping=g_acc=k, g_q, g_v
    dim3 gg(M_/128, 3);
    k_gemm<<<gg, 256>>>(x, Wk, Wq, Wv);

    // two sparse propagation iterations, accumulating into g_acc
    k_spmm<<<N_, 128>>>(0, 1);   // it1 = S@(decay*k)     -> g_pong, acc += it1
    k_spmm<<<N_, 128>>>(1, 0);   // it2 = S@(decay*it1)   -> acc += it2

    // w, scale, layernorm, shuffled output
    k_final<<<M_, 128>>>(gamma, beta, out);
}

// round 7
// speedup vs baseline: 2.8141x; 2.8141x over previous
#include <cuda_runtime.h>
#include <cuda_bf16.h>
#include <cstdint>

// ---------------- problem constants ----------------
#define B_   16
#define N_   10000
#define C_   256
#define H_   4
#define KD_  16
#define E_   320000
#define F_   1024          // B*H*KD per-node feature width
#define M_   (B_*N_)       // 160000 rows

// ---------------- device scratch ----------------
__device__ __align__(16) float g_q   [(size_t)M_*64];    // [r=b*N+n][h*16+kd]
__device__ __align__(16) float g_v   [(size_t)M_*256];   // [r][c]
__device__ __align__(16) float g_ping[(size_t)N_*F_];    // it buffers [n][b*64+h*16+kd]
__device__ __align__(16) float g_pong[(size_t)N_*F_];
__device__ __align__(16) float g_acc [(size_t)N_*F_];    // accumulated k
__device__ int   g_rowptr[N_+1];
__device__ int   g_fill  [N_];
__device__ int   g_cols  [E_];
__device__ float g_vals  [E_];
// pre-split B images: [nt(3)][n(128)][k(256)] bf16, k contiguous (col-major KxN per tile)
__device__ __align__(16) __nv_bfloat16 g_Bh[3*128*256];
__device__ __align__(16) __nv_bfloat16 g_Bl[3*128*256];

// ---------------- CSR build ----------------
__global__ void k_zero_counts() {
    int i = blockIdx.x*blockDim.x + threadIdx.x;
    if (i < N_) g_fill[i] = 0;
}
__global__ void k_hist(const int* __restrict__ rows) {
    int e = blockIdx.x*blockDim.x + threadIdx.x;
    if (e < E_) atomicAdd(&g_fill[rows[e]], 1);
}
__global__ void k_scan() {
    __shared__ int sm[1024];
    int carry = 0;
    int tid = threadIdx.x;
    for (int base = 0; base < N_; base += 1024) {
        int idx = base + tid;
        int v = (idx < N_) ? g_fill[idx] : 0;
        sm[tid] = v;
        __syncthreads();
        for (int off = 1; off < 1024; off <<= 1) {
            int t = (tid >= off) ? sm[tid-off] : 0;
            __syncthreads();
            sm[tid] += t;
            __syncthreads();
        }
        int incl = sm[tid];
        if (idx < N_) {
            int ex = carry + incl - v;
            g_rowptr[idx] = ex;
            g_fill[idx]   = ex;
        }
        carry += sm[1023];
        __syncthreads();
    }
    if (tid == 0) g_rowptr[N_] = carry;
}
__global__ void k_scatter(const int* __restrict__ rows, const int* __restrict__ cols,
                          const float* __restrict__ vals) {
    int e = blockIdx.x*blockDim.x + threadIdx.x;
    if (e < E_) {
        int r = rows[e];
        int pos = atomicAdd(&g_fill[r], 1);
        g_cols[pos] = cols[e];
        g_vals[pos] = vals[e];
    }
}

// ---------------- prep: split B into hi/lo bf16 images, [nt][n][k] ----------------
// nt0 n: 0..63 = Wk cols, 64..127 = Wq cols; nt1: Wv 0..127; nt2: Wv 128..255
__global__ void k_prepB(const float* __restrict__ Wk, const float* __restrict__ Wq,
                        const float* __restrict__ Wv) {
    int idx = blockIdx.x*blockDim.x + threadIdx.x;
    if (idx >= 3*128*256) return;
    int nt  = idx >> 15;
    int rem = idx & 32767;
    int n   = rem >> 8;
    int k   = rem & 255;
    float w;
    if (nt == 0)      w = (n < 64) ? Wk[k*64 + n] : Wq[k*64 + (n - 64)];
    else if (nt == 1) w = Wv[k*256 + n];
    else              w = Wv[k*256 + 128 + n];
    __nv_bfloat16 hi = __float2bfloat16(w);
    __nv_bfloat16 lo = __float2bfloat16(w - __bfloat162float(hi));
    g_Bh[idx] = hi;
    g_Bl[idx] = lo;
}

// ---------------- mma.sync GEMM (bf16 split, HMMA path) ----------------
__device__ __forceinline__ void split2(float f0, float f1, uint32_t& h, uint32_t& l) {
    __nv_bfloat16 h0 = __float2bfloat16(f0);
    __nv_bfloat16 h1 = __float2bfloat16(f1);
    __nv_bfloat16 l0 = __float2bfloat16(f0 - __bfloat162float(h0));
    __nv_bfloat16 l1 = __float2bfloat16(f1 - __bfloat162float(h1));
    h = (uint32_t)__bfloat16_as_ushort(h0) | ((uint32_t)__bfloat16_as_ushort(h1) << 16);
    l = (uint32_t)__bfloat16_as_ushort(l0) | ((uint32_t)__bfloat16_as_ushort(l1) << 16);
}

__device__ __forceinline__ uint32_t smem_u32(const void* p) {
    uint32_t a;
    asm("{ .reg .u64 t; cvta.to.shared.u64 t, %1; cvt.u32.u64 %0, t; }" : "=r"(a) : "l"(p));
    return a;
}

__device__ __forceinline__ void ldm_x4(uint32_t r[4], uint32_t addr) {
    asm volatile("ldmatrix.sync.aligned.m8n8.x4.shared.b16 {%0,%1,%2,%3}, [%4];"
        : "=r"(r[0]), "=r"(r[1]), "=r"(r[2]), "=r"(r[3]) : "r"(addr));
}

__device__ __forceinline__ void mma16816(float c[4], const uint32_t a[4],
                                         const uint32_t b0, const uint32_t b1) {
    asm volatile(
        "mma.sync.aligned.m16n8k16.row.col.f32.bf16.bf16.f32 "
        "{%0,%1,%2,%3}, {%4,%5,%6,%7}, {%8,%9}, {%0,%1,%2,%3};"
        : "+f"(c[0]), "+f"(c[1]), "+f"(c[2]), "+f"(c[3])
        : "r"(a[0]), "r"(a[1]), "r"(a[2]), "r"(a[3]), "r"(b0), "r"(b1));
}

// smem tiles: 128 rows x 32 bf16, row stride 112 B (16B-aligned, conflict-free ldmatrix)
#define ROWB  112
#define AH_OFF 0
#define AL_OFF 14336
#define BH_OFF 28672
#define BL_OFF 43008
#define SMEM_TOTAL 57344

__global__ __launch_bounds__(256) void k_tgemm(const float* __restrict__ x) {
    extern __shared__ char smem[];
    const uint32_t sb = smem_u32(smem);
    const int tid  = threadIdx.x;
    const int wid  = tid >> 5;
    const int lane = tid & 31;
    const int wm   = wid & 3;        // 4 M-slices of 32 rows
    const int wn   = wid >> 2;       // 2 N-slices of 64 cols
    const int m0   = blockIdx.x * 128;
    const int ct   = blockIdx.y;     // 0: k|q, 1: v[0:128], 2: v[128:256]

    // per-thread staging: row r = tid>>1, k-half h = tid&1 (16 k values)
    const int r  = tid >> 1;
    const int hh = tid & 1;
    const float4* xrow0 = (const float4*)(x + (size_t)(m0 + r) * 256 + hh * 16);
    const uint4* bhp0 = (const uint4*)(g_Bh + ((size_t)(ct * 128 + r)) * 256 + hh * 16);
    const uint4* blp0 = (const uint4*)(g_Bl + ((size_t)(ct * 128 + r)) * 256 + hh * 16);

    float acc[2][8][4];
    #pragma unroll
    for (int mt = 0; mt < 2; mt++)
        #pragma unroll
        for (int nf = 0; nf < 8; nf++)
            #pragma unroll
            for (int j = 0; j < 4; j++) acc[mt][nf][j] = 0.f;

    // ldmatrix lane addresses (row within tile = l&15; +16B for upper half lanes)
    const int lrow = lane & 15;
    const int lcol = (lane >> 4) * 16;
    uint32_t aAH[2], aAL[2], aBH[4], aBL[4];
    #pragma unroll
    for (int mt = 0; mt < 2; mt++) {
        uint32_t ro = (uint32_t)(wm*32 + mt*16 + lrow) * ROWB + lcol;
        aAH[mt] = sb + AH_OFF + ro;
        aAL[mt] = sb + AL_OFF + ro;
    }
    #pragma unroll
    for (int bt = 0; bt < 4; bt++) {
        uint32_t ro = (uint32_t)(wn*64 + bt*16 + lrow) * ROWB + lcol;
        aBH[bt] = sb + BH_OFF + ro;
        aBL[bt] = sb + BL_OFF + ro;
    }

    // prefetch chunk 0
    float4 xs0 = xrow0[0], xs1 = xrow0[1], xs2 = xrow0[2], xs3 = xrow0[3];
    uint4  bhs0 = bhp0[0], bhs1 = bhp0[1];
    uint4  bls0 = blp0[0], bls1 = blp0[1];

    char* const arow = smem + (size_t)r * ROWB + hh * 32;

    #pragma unroll 1
    for (int kc = 0; kc < 8; kc++) {
        // ---- store staged chunk into smem (fp32 -> bf16 hi/lo split for A) ----
        __syncthreads();                 // previous chunk's MMAs done
        {
            uint32_t h0,l0,h1,l1,h2,l2,h3,l3,h4,l4,h5,l5,h6,l6,h7,l7;
            split2(xs0.x, xs0.y, h0, l0); split2(xs0.z, xs0.w, h1, l1);
            split2(xs1.x, xs1.y, h2, l2); split2(xs1.z, xs1.w, h3, l3);
            split2(xs2.x, xs2.y, h4, l4); split2(xs2.z, xs2.w, h5, l5);
            split2(xs3.x, xs3.y, h6, l6); split2(xs3.z, xs3.w, h7, l7);
            *(uint4*)(arow + AH_OFF)      = make_uint4(h0,h1,h2,h3);
            *(uint4*)(arow + AH_OFF + 16) = make_uint4(h4,h5,h6,h7);
            *(uint4*)(arow + AL_OFF)      = make_uint4(l0,l1,l2,l3);
            *(uint4*)(arow + AL_OFF + 16) = make_uint4(l4,l5,l6,l7);
            *(uint4*)(arow + BH_OFF)      = bhs0;
            *(uint4*)(arow + BH_OFF + 16) = bhs1;
            *(uint4*)(arow + BL_OFF)      = bls0;
            *(uint4*)(arow + BL_OFF + 16) = bls1;
        }
        __syncthreads();

        // ---- prefetch next chunk (hidden behind the MMA stream) ----
        if (kc < 7) {
            const float4* xp = xrow0 + (kc + 1) * 8;   // +32 floats
            xs0 = xp[0]; xs1 = xp[1]; xs2 = xp[2]; xs3 = xp[3];
            const uint4* bp = bhp0 + (kc + 1) * 4;     // +32 bf16
            bhs0 = bp[0]; bhs1 = bp[1];
            const uint4* lp = blp0 + (kc + 1) * 4;
            bls0 = lp[0]; bls1 = lp[1];
        }

        // ---- MMA: 2 k16 steps x 3 split terms ----
        #pragma unroll
        for (int ks = 0; ks < 2; ks++) {
            uint32_t ah[2][4], al[2][4], bh[8][2], bl[8][2];
            #pragma unroll
            for (int mt = 0; mt < 2; mt++) {
                ldm_x4(ah[mt], aAH[mt] + ks*32);
                ldm_x4(al[mt], aAL[mt] + ks*32);
            }
            #pragma unroll
            for (int bt = 0; bt < 4; bt++) {
                uint32_t t[4];
                ldm_x4(t, aBH[bt] + ks*32);
                bh[2*bt][0] = t[0]; bh[2*bt][1] = t[2];
                bh[2*bt+1][0] = t[1]; bh[2*bt+1][1] = t[3];
                ldm_x4(t, aBL[bt] + ks*32);
                bl[2*bt][0] = t[0]; bl[2*bt][1] = t[2];
                bl[2*bt+1][0] = t[1]; bl[2*bt+1][1] = t[3];
            }
            #pragma unroll
            for (int mt = 0; mt < 2; mt++)
                #pragma unroll
                for (int nf = 0; nf < 8; nf++)
                    mma16816(acc[mt][nf], ah[mt], bh[nf][0], bh[nf][1]);
            #pragma unroll
            for (int mt = 0; mt < 2; mt++)
                #pragma unroll
                for (int nf = 0; nf < 8; nf++)
                    mma16816(acc[mt][nf], ah[mt], bl[nf][0], bl[nf][1]);
            #pragma unroll
            for (int mt = 0; mt < 2; mt++)
                #pragma unroll
                for (int nf = 0; nf < 8; nf++)
                    mma16816(acc[mt][nf], al[mt], bh[nf][0], bh[nf][1]);
        }
    }

    // ---- fused epilogue: route D frags ----
    const int qr = lane >> 2;          // 0..7
    const int qc = (lane & 3) * 2;     // 0,2,4,6
    #pragma unroll
    for (int mt = 0; mt < 2; mt++) {
        #pragma unroll
        for (int half = 0; half < 2; half++) {
            int m  = m0 + wm*32 + mt*16 + qr + half*8;
            int bb = m / N_, nn = m - bb * N_;
            #pragma unroll
            for (int nf = 0; nf < 8; nf++) {
                int c = wn*64 + nf*8 + qc;
                float v0 = acc[mt][nf][half*2 + 0];
                float v1 = acc[mt][nf][half*2 + 1];
                if (ct == 0) {
                    v0 = (v0 > 0.f) ? (v0 + 1.f) : __expf(v0);
                    v1 = (v1 > 0.f) ? (v1 + 1.f) : __expf(v1);
                    if (c < 64) {
                        float2 t = make_float2(v0, v1);
                        *(float2*)(g_ping + (size_t)nn*F_ + bb*64 + c) = t;
                        *(float2*)(g_acc  + (size_t)nn*F_ + bb*64 + c) = t;
                    } else {
                        *(float2*)(g_q + (size_t)m*64 + (c - 64)) = make_float2(v0, v1);
                    }
                } else {
                    *(float2*)(g_v + (size_t)m*256 + (ct - 1)*128 + c) = make_float2(v0, v1);
                }
            }
        }
    }
}

// ---------------- sparse propagation ----------------
__device__ __forceinline__ float4 f4fma(float s, float4 x, float4 a) {
    a.x = fmaf(s, x.x, a.x); a.y = fmaf(s, x.y, a.y);
    a.z = fmaf(s, x.z, a.z); a.w = fmaf(s, x.w, a.w);
    return a;
}

__global__ __launch_bounds__(128) void k_spmm(int srcsel, int store) {
    const float4* __restrict__ S = (const float4*)(srcsel ? g_pong : g_ping);
    float4* __restrict__ D       = (float4*)(srcsel ? g_ping : g_pong);
    const int r = blockIdx.x;
    const int t = threadIdx.x;
    const int e0 = g_rowptr[r], e1 = g_rowptr[r+1];

    float4 s0 = make_float4(0.f,0.f,0.f,0.f);
    float4 s1 = make_float4(0.f,0.f,0.f,0.f);

    #pragma unroll 4
    for (int e = e0; e < e1; e++) {
        int   c = __ldg(&g_cols[e]);
        float v = __ldg(&g_vals[e]);
        const float4* p = S + (size_t)c * 256;
        s0 = f4fma(v, __ldg(&p[t]),       s0);
        s1 = f4fma(v, __ldg(&p[128 + t]), s1);
    }

    const int   h   = (t & 15) >> 2;
    const float dec = 0.1f + (float)h * (0.4f/3.0f);
    s0.x *= dec; s0.y *= dec; s0.z *= dec; s0.w *= dec;
    s1.x *= dec; s1.y *= dec; s1.z *= dec; s1.w *= dec;

    float4* A = (float4*)g_acc + (size_t)r * 256;
    float4 a0 = A[t];       a0.x += s0.x; a0.y += s0.y; a0.z += s0.z; a0.w += s0.w; A[t] = a0;
    float4 a1 = A[128 + t]; a1.x += s1.x; a1.y += s1.y; a1.z += s1.z; a1.w += s1.w; A[128 + t] = a1;

    if (store) {
        D[(size_t)r*256 + t]       = s0;
        D[(size_t)r*256 + 128 + t] = s1;
    }
}

// ---------------- fused final ----------------
__global__ __launch_bounds__(128) void k_final(const float* __restrict__ gamma,
                                               const float* __restrict__ beta,
                                               float* __restrict__ out) {
    const int r  = blockIdx.x;
    const int bb = r / N_, nn = r % N_;
    const int w  = threadIdx.x >> 5;
    const int l  = threadIdx.x & 31;

    float p = 0.f;
    if (l < 16)
        p = g_acc[nn*F_ + bb*64 + w*16 + l] * g_q[(size_t)r*64 + w*16 + l];
    #pragma unroll
    for (int off = 16; off; off >>= 1) p += __shfl_xor_sync(0xffffffffu, p, off);
    const float wv = p * (1.0f/16.0f);

    const float* vp = g_v + (size_t)r*256 + w*64;
    float v0 = vp[l]      * wv;
    float v1 = vp[32 + l] * wv;

    float s  = v0 + v1;
    float s2 = fmaf(v0, v0, v1*v1);
    #pragma unroll
    for (int off = 16; off; off >>= 1) {
        s  += __shfl_xor_sync(0xffffffffu, s,  off);
        s2 += __shfl_xor_sync(0xffffffffu, s2, off);
    }
    const float mu  = s  * (1.0f/64.0f);
    const float var = s2 * (1.0f/64.0f) - mu*mu;
    const float inv = rsqrtf(var + 1e-5f);

    float* op = out + (size_t)((r % B_)*N_ + r / B_) * 256 + w*64;
    op[l]      = (v0 - mu)*inv*gamma[l]      + beta[l];
    op[32 + l] = (v1 - mu)*inv*gamma[32 + l] + beta[32 + l];
}

// ---------------- launch ----------------
extern "C" void kernel_launch(void* const* d_in, const int* in_sizes, int n_in,
                              void* d_out, int out_size) {
    const float* x     = (const float*)d_in[0];
    const float* evals = (const float*)d_in[1];
    const float* Wk    = (const float*)d_in[2];
    const float* Wq    = (const float*)d_in[3];
    const float* Wv    = (const float*)d_in[4];
    const float* gamma = (const float*)d_in[5];
    const float* beta  = (const float*)d_in[6];
    const int*   erows = (const int*)d_in[7];
    const int*   ecols = (const int*)d_in[8];
    float* out = (float*)d_out;

    cudaFuncSetAttribute(k_tgemm, cudaFuncAttributeMaxDynamicSharedMemorySize, SMEM_TOTAL);

    // CSR build
    k_zero_counts<<<(N_ + 255)/256, 256>>>();
    k_hist<<<(E_ + 255)/256, 256>>>(erows);
    k_scan<<<1, 1024>>>();
    k_scatter<<<(E_ + 255)/256, 256>>>(erows, ecols, evals);

    // B split prep + tensor-core GEMM (fused elu+1 epilogue)
    k_prepB<<<384, 256>>>(Wk, Wq, Wv);
    dim3 gg(M_/128, 3);
    k_tgemm<<<gg, 256, SMEM_TOTAL>>>(x);

    // sparse propagation
    k_spmm<<<N_, 128>>>(0, 1);
    k_spmm<<<N_, 128>>>(1, 0);

    // epilogue
    k_final<<<M_, 128>>>(gamma, beta, out);
}